// round 3
// baseline (speedup 1.0000x reference)
#include <cuda_runtime.h>
#include <cuda_bf16.h>
#include <cstdint>

#define N_NODES 100000
#define N_EDGES 1600000
#define N_GRAPHS 512
#define HID 128
#define N_CLS 10
#define ALPHA 0.01f

// ---------------- scratch (device globals; no runtime allocation) -------------
__device__ float g_hlin[(size_t)N_NODES * HID];
__device__ float g_h0  [(size_t)N_NODES * HID];
__device__ float g_h1  [(size_t)N_NODES * HID];
__device__ float g_h2  [(size_t)N_NODES * HID];
__device__ float g_h3  [(size_t)N_NODES * HID];
__device__ float g_ht  [(size_t)N_NODES * HID];

__device__ int      g_counts [N_NODES];
__device__ int      g_rowptr [N_NODES + 1];
__device__ int      g_cursor [N_NODES];
__device__ int      g_esrc   [N_EDGES];
__device__ int      g_partials[128];
__device__ unsigned g_pool   [N_GRAPHS * 4 * HID];   // ordered-uint encoded max

// device-side buffer selector (avoids cudaGetSymbolAddress on host)
__device__ __forceinline__ float* buf_ptr(int id) {
    switch (id) {
        case 0: return g_hlin;
        case 1: return g_h0;
        case 2: return g_h1;
        case 3: return g_h2;
        case 4: return g_h3;
        default: return g_ht;
    }
}

// ---------------- helpers ----------------------------------------------------
__device__ __forceinline__ unsigned f2ord(float v) {
    unsigned u = __float_as_uint(v);
    return (u & 0x80000000u) ? ~u : (u | 0x80000000u);
}
__device__ __forceinline__ float ord2f(unsigned e) {
    unsigned u = (e & 0x80000000u) ? (e & 0x7FFFFFFFu) : ~e;
    return __uint_as_float(u);
}

// ---------------- CSR build --------------------------------------------------
__global__ void init_kernel() {
    int i = blockIdx.x * blockDim.x + threadIdx.x;
    if (i < N_NODES) g_counts[i] = 0;
    if (i < N_GRAPHS * 4 * HID) g_pool[i] = 0x007FFFFFu;  // f2ord(-inf)
}

__global__ void hist_kernel(const int* __restrict__ dst) {
    int i = blockIdx.x * blockDim.x + threadIdx.x;
    if (i < N_EDGES) atomicAdd(&g_counts[dst[i]], 1);
}

// 1024 elems per block (256 thr x 4), exclusive scan within block
__global__ void scan1_kernel() {
    __shared__ int sm[256];
    int b = blockIdx.x, t = threadIdx.x;
    int base = b * 1024 + t * 4;
    int v0 = (base + 0 < N_NODES) ? g_counts[base + 0] : 0;
    int v1 = (base + 1 < N_NODES) ? g_counts[base + 1] : 0;
    int v2 = (base + 2 < N_NODES) ? g_counts[base + 2] : 0;
    int v3 = (base + 3 < N_NODES) ? g_counts[base + 3] : 0;
    int tot = v0 + v1 + v2 + v3;
    sm[t] = tot;
    __syncthreads();
    for (int off = 1; off < 256; off <<= 1) {
        int y = (t >= off) ? sm[t - off] : 0;
        __syncthreads();
        sm[t] += y;
        __syncthreads();
    }
    int excl = sm[t] - tot;
    if (base + 0 < N_NODES) g_rowptr[base + 0] = excl;
    if (base + 1 < N_NODES) g_rowptr[base + 1] = excl + v0;
    if (base + 2 < N_NODES) g_rowptr[base + 2] = excl + v0 + v1;
    if (base + 3 < N_NODES) g_rowptr[base + 3] = excl + v0 + v1 + v2;
    if (t == 255) g_partials[b] = sm[255];
}

__global__ void scan2_kernel(int nblocks) {
    if (threadIdx.x == 0 && blockIdx.x == 0) {
        int run = 0;
        for (int i = 0; i < nblocks; i++) { int c = g_partials[i]; g_partials[i] = run; run += c; }
    }
}

__global__ void scan3_kernel() {
    int i = blockIdx.x * blockDim.x + threadIdx.x;
    if (i < N_NODES) {
        int v = g_rowptr[i] + g_partials[i >> 10];
        g_rowptr[i] = v;
        g_cursor[i] = v;
    }
    if (i == 0) g_rowptr[N_NODES] = N_EDGES;
}

__global__ void scatter_kernel(const int* __restrict__ src, const int* __restrict__ dst) {
    int i = blockIdx.x * blockDim.x + threadIdx.x;
    if (i < N_EDGES) {
        int p = atomicAdd(&g_cursor[dst[i]], 1);
        g_esrc[p] = src[i];
    }
}

// ---------------- GEMM: g_hlin[M,128] = A[M,128] @ W[128,128] + b ------------
// 256 threads, tile 64 rows x 128 cols. Static smem <= 48KB:
// stage half of W (64x128 = 32KB) + half-K A tile (64x64 = 16KB); 2 K-passes.
// in_id: 6 = external x pointer (use xin), else buf_ptr(in_id).
__global__ void gemm128_kernel(const float* __restrict__ xin, int in_id,
                               const float* __restrict__ W,
                               const float* __restrict__ bias, int M) {
    __shared__ float Ws[64 * 128];   // W[k0+0..63][0..127]
    __shared__ float As[64 * 64];    // A[rows][k0+0..63]
    const float* A = (in_id == 6) ? xin : buf_ptr(in_id);
    float* C = g_hlin;
    int tx = threadIdx.x;
    int row0 = blockIdx.x * 64;

    int tm = tx >> 5;   // 0..7 -> 8 rows each
    int tn = tx & 31;   // 0..31 -> 4 cols each
    float4 bb = ((const float4*)bias)[tn];
    float acc[8][4];
    #pragma unroll
    for (int r = 0; r < 8; r++) {
        acc[r][0] = bb.x; acc[r][1] = bb.y; acc[r][2] = bb.z; acc[r][3] = bb.w;
    }

    for (int kp = 0; kp < 2; kp++) {
        int k0 = kp * 64;
        // load W[k0 .. k0+63][:]  (64*32 float4)
        const float4* W4 = (const float4*)(W + (size_t)k0 * 128);
        float4* Ws4 = (float4*)Ws;
        #pragma unroll
        for (int i = tx; i < 64 * 32; i += 256) Ws4[i] = W4[i];
        // load A[row0 .. row0+63][k0 .. k0+63]  (64*16 float4)
        float4* As4 = (float4*)As;
        #pragma unroll
        for (int i = tx; i < 64 * 16; i += 256) {
            int r = i >> 4, c = i & 15;
            float4 v = make_float4(0.f, 0.f, 0.f, 0.f);
            if (row0 + r < M) v = ((const float4*)(A + (size_t)(row0 + r) * 128 + k0))[c];
            As4[i] = v;
        }
        __syncthreads();

        #pragma unroll 8
        for (int k = 0; k < 64; k++) {
            float4 w = ((float4*)Ws)[k * 32 + tn];
            #pragma unroll
            for (int r = 0; r < 8; r++) {
                float a = As[(tm * 8 + r) * 64 + k];
                acc[r][0] += a * w.x;
                acc[r][1] += a * w.y;
                acc[r][2] += a * w.z;
                acc[r][3] += a * w.w;
            }
        }
        __syncthreads();
    }

    #pragma unroll
    for (int r = 0; r < 8; r++) {
        int row = row0 + tm * 8 + r;
        if (row < M)
            ((float4*)C)[(size_t)row * 32 + tn] =
                make_float4(acc[r][0], acc[r][1], acc[r][2], acc[r][3]);
    }
}

// ---------------- aggregation: pull-style mean + leaky relu ------------------
// one warp per node; lane owns float4 (4 consecutive features)
// out_id selects destination buffer; do_resid: also write g_h3 = g_h0 + result
__global__ void agg_kernel(int out_id, int do_resid) {
    int node = (blockIdx.x * blockDim.x + threadIdx.x) >> 5;
    int lane = threadIdx.x & 31;
    if (node >= N_NODES) return;
    const float* hlin = g_hlin;
    float* out = buf_ptr(out_id);
    int s0 = g_rowptr[node];
    int s1 = g_rowptr[node + 1];
    float4 acc = make_float4(0.f, 0.f, 0.f, 0.f);
    for (int e = s0; e < s1; e++) {
        int s = g_esrc[e];
        float4 v = __ldg(((const float4*)(hlin + (size_t)s * HID)) + lane);
        acc.x += v.x; acc.y += v.y; acc.z += v.z; acc.w += v.w;
    }
    float inv = 1.0f / fmaxf((float)(s1 - s0), 1.0f);
    acc.x *= inv; acc.y *= inv; acc.z *= inv; acc.w *= inv;
    acc.x = (acc.x > 0.f) ? acc.x : ALPHA * acc.x;
    acc.y = (acc.y > 0.f) ? acc.y : ALPHA * acc.y;
    acc.z = (acc.z > 0.f) ? acc.z : ALPHA * acc.z;
    acc.w = (acc.w > 0.f) ? acc.w : ALPHA * acc.w;
    ((float4*)out)[(size_t)node * 32 + lane] = acc;
    if (do_resid) {
        float4 r = ((const float4*)g_h0)[(size_t)node * 32 + lane];
        r.x += acc.x; r.y += acc.y; r.z += acc.z; r.w += acc.w;
        ((float4*)g_h3)[(size_t)node * 32 + lane] = r;
    }
}

// ---------------- segment-max pooling (sorted-batch running max) --------------
// 128 threads/block; thread t owns cols [4t, 4t+4) of the 512-wide concat.
// Walk NODES_PER_BLOCK consecutive nodes, flush atomics only on graph change.
#define NODES_PER_BLOCK 128
__global__ void pool_kernel(const int* __restrict__ batch) {
    int t = threadIdx.x;
    int n0 = blockIdx.x * NODES_PER_BLOCK;
    int n1 = n0 + NODES_PER_BLOCK;
    if (n1 > N_NODES) n1 = N_NODES;
    if (n0 >= N_NODES) return;

    const float* srcp;
    int off;
    if (t < 32)      { srcp = g_ht; off = t; }
    else if (t < 64) { srcp = g_h1; off = t - 32; }
    else if (t < 96) { srcp = g_h2; off = t - 64; }
    else             { srcp = g_h3; off = t - 96; }

    const float NEG = -__int_as_float(0x7f800000);  // -inf
    float4 acc = make_float4(NEG, NEG, NEG, NEG);
    int cur = batch[n0];

    for (int n = n0; n < n1; n++) {
        int g = batch[n];   // uniform across block (sorted batch)
        if (g != cur) {
            unsigned* p = &g_pool[cur * 512 + t * 4];
            atomicMax(p + 0, f2ord(acc.x));
            atomicMax(p + 1, f2ord(acc.y));
            atomicMax(p + 2, f2ord(acc.z));
            atomicMax(p + 3, f2ord(acc.w));
            acc = make_float4(NEG, NEG, NEG, NEG);
            cur = g;
        }
        float4 v = ((const float4*)(srcp + (size_t)n * HID))[off];
        acc.x = fmaxf(acc.x, v.x);
        acc.y = fmaxf(acc.y, v.y);
        acc.z = fmaxf(acc.z, v.z);
        acc.w = fmaxf(acc.w, v.w);
    }
    unsigned* p = &g_pool[cur * 512 + t * 4];
    atomicMax(p + 0, f2ord(acc.x));
    atomicMax(p + 1, f2ord(acc.y));
    atomicMax(p + 2, f2ord(acc.z));
    atomicMax(p + 3, f2ord(acc.w));
}

// ---------------- MLP head ---------------------------------------------------
__global__ void mlp_kernel(const float* __restrict__ Wm1, const float* __restrict__ bm1,
                           const float* __restrict__ gamma, const float* __restrict__ beta,
                           const float* __restrict__ Wm2, const float* __restrict__ bm2,
                           float* __restrict__ out) {
    __shared__ float ps[512];
    __shared__ float zs[128];
    int g = blockIdx.x;
    int t = threadIdx.x;
    for (int i = t; i < 512; i += 128) ps[i] = ord2f(g_pool[g * 512 + i]);
    __syncthreads();
    float acc = bm1[t];
    #pragma unroll 8
    for (int i = 0; i < 512; i++) acc += ps[i] * Wm1[i * 128 + t];
    const float rs = rsqrtf(1.0f + 1e-5f);
    acc = (acc * gamma[t]) * rs + beta[t];
    zs[t] = fmaxf(acc, 0.0f);
    __syncthreads();
    if (t < N_CLS) {
        float o = bm2[t];
        #pragma unroll 8
        for (int k = 0; k < 128; k++) o += zs[k] * Wm2[k * N_CLS + t];
        out[g * N_CLS + t] = o;
    }
}

// ---------------- launch -----------------------------------------------------
extern "C" void kernel_launch(void* const* d_in, const int* in_sizes, int n_in,
                              void* d_out, int out_size) {
    (void)in_sizes; (void)n_in; (void)out_size;
    const float* x     = (const float*)d_in[0];
    const int*   ei    = (const int*)d_in[1];
    const int*   batch = (const int*)d_in[2];
    const float* W0 = (const float*)d_in[3];
    const float* b0 = (const float*)d_in[4];
    const float* W1 = (const float*)d_in[5];
    const float* b1 = (const float*)d_in[6];
    const float* W2 = (const float*)d_in[7];
    const float* b2 = (const float*)d_in[8];
    const float* W3 = (const float*)d_in[9];
    const float* b3 = (const float*)d_in[10];
    const float* Wm1 = (const float*)d_in[11];
    const float* bm1 = (const float*)d_in[12];
    const float* gamma = (const float*)d_in[13];
    const float* beta  = (const float*)d_in[14];
    const float* Wm2 = (const float*)d_in[15];
    const float* bm2 = (const float*)d_in[16];
    float* out = (float*)d_out;

    const int* src = ei;
    const int* dst = ei + N_EDGES;

    const int SCAN_BLOCKS = (N_NODES + 1023) / 1024;  // 98

    // CSR build
    init_kernel<<<(N_GRAPHS * 4 * HID + 255) / 256, 256>>>();
    hist_kernel<<<(N_EDGES + 255) / 256, 256>>>(dst);
    scan1_kernel<<<SCAN_BLOCKS, 256>>>();
    scan2_kernel<<<1, 32>>>(SCAN_BLOCKS);
    scan3_kernel<<<(N_NODES + 255) / 256, 256>>>();
    scatter_kernel<<<(N_EDGES + 255) / 256, 256>>>(src, dst);

    const int GEMM_GRID = (N_NODES + 63) / 64;
    const int AGG_GRID  = (N_NODES * 32 + 255) / 256;

    // buffer ids: 0=hlin 1=h0 2=h1 3=h2 4=h3 5=ht 6=external x
    // layer 0 (init_graph): hlin = x@W0+b0 ; h0 = agg
    gemm128_kernel<<<GEMM_GRID, 256>>>(x, 6, W0, b0, N_NODES);
    agg_kernel<<<AGG_GRID, 256>>>(1, 0);
    // layer 1 (head): hlin = h0@W1+b1 ; h1 = agg
    gemm128_kernel<<<GEMM_GRID, 256>>>(nullptr, 1, W1, b1, N_NODES);
    agg_kernel<<<AGG_GRID, 256>>>(2, 0);
    // layer 2 (body): hlin = h1@W2+b2 ; h2 = agg ; h3 = h0 + h2
    gemm128_kernel<<<GEMM_GRID, 256>>>(nullptr, 2, W2, b2, N_NODES);
    agg_kernel<<<AGG_GRID, 256>>>(3, 1);
    // layer 3 (tail): hlin = h3@W3+b3 ; ht = agg
    gemm128_kernel<<<GEMM_GRID, 256>>>(nullptr, 4, W3, b3, N_NODES);
    agg_kernel<<<AGG_GRID, 256>>>(5, 0);

    // pooling + head MLP
    pool_kernel<<<(N_NODES + NODES_PER_BLOCK - 1) / NODES_PER_BLOCK, 128>>>(batch);
    mlp_kernel<<<N_GRAPHS, 128>>>(Wm1, bm1, gamma, beta, Wm2, bm2, out);
}

// round 4
// speedup vs baseline: 1.0690x; 1.0690x over previous
#include <cuda_runtime.h>
#include <cuda_bf16.h>
#include <cstdint>

#define N_NODES 100000
#define N_EDGES 1600000
#define N_GRAPHS 512
#define HID 128
#define N_CLS 10
#define ALPHA 0.01f

// ---------------- scratch (device globals; no runtime allocation) -------------
__device__ float g_hlin[(size_t)N_NODES * HID];
__device__ float g_h0  [(size_t)N_NODES * HID];
__device__ float g_h1  [(size_t)N_NODES * HID];
__device__ float g_h2  [(size_t)N_NODES * HID];
__device__ float g_h3  [(size_t)N_NODES * HID];
__device__ float g_ht  [(size_t)N_NODES * HID];

__device__ int      g_counts [N_NODES];
__device__ int      g_rowptr [N_NODES + 1];
__device__ int      g_cursor [N_NODES];
__device__ int      g_esrc   [N_EDGES];
__device__ int      g_partials[128];
__device__ unsigned g_pool   [N_GRAPHS * 4 * HID];   // ordered-uint encoded max

// device-side buffer selector (avoids cudaGetSymbolAddress on host)
__device__ __forceinline__ float* buf_ptr(int id) {
    switch (id) {
        case 0: return g_hlin;
        case 1: return g_h0;
        case 2: return g_h1;
        case 3: return g_h2;
        case 4: return g_h3;
        default: return g_ht;
    }
}

// ---------------- helpers ----------------------------------------------------
__device__ __forceinline__ unsigned f2ord(float v) {
    unsigned u = __float_as_uint(v);
    return (u & 0x80000000u) ? ~u : (u | 0x80000000u);
}
__device__ __forceinline__ float ord2f(unsigned e) {
    unsigned u = (e & 0x80000000u) ? (e & 0x7FFFFFFFu) : ~e;
    return __uint_as_float(u);
}

// ---------------- CSR build --------------------------------------------------
__global__ void init_kernel() {
    int i = blockIdx.x * blockDim.x + threadIdx.x;
    if (i < N_NODES) g_counts[i] = 0;
    if (i < N_GRAPHS * 4 * HID) g_pool[i] = 0x007FFFFFu;  // f2ord(-inf)
}

__global__ void hist_kernel(const int* __restrict__ dst) {
    int i = blockIdx.x * blockDim.x + threadIdx.x;
    if (i < N_EDGES) atomicAdd(&g_counts[dst[i]], 1);
}

// 1024 elems per block (256 thr x 4), exclusive scan within block
__global__ void scan1_kernel() {
    __shared__ int sm[256];
    int b = blockIdx.x, t = threadIdx.x;
    int base = b * 1024 + t * 4;
    int v0 = (base + 0 < N_NODES) ? g_counts[base + 0] : 0;
    int v1 = (base + 1 < N_NODES) ? g_counts[base + 1] : 0;
    int v2 = (base + 2 < N_NODES) ? g_counts[base + 2] : 0;
    int v3 = (base + 3 < N_NODES) ? g_counts[base + 3] : 0;
    int tot = v0 + v1 + v2 + v3;
    sm[t] = tot;
    __syncthreads();
    for (int off = 1; off < 256; off <<= 1) {
        int y = (t >= off) ? sm[t - off] : 0;
        __syncthreads();
        sm[t] += y;
        __syncthreads();
    }
    int excl = sm[t] - tot;
    if (base + 0 < N_NODES) g_rowptr[base + 0] = excl;
    if (base + 1 < N_NODES) g_rowptr[base + 1] = excl + v0;
    if (base + 2 < N_NODES) g_rowptr[base + 2] = excl + v0 + v1;
    if (base + 3 < N_NODES) g_rowptr[base + 3] = excl + v0 + v1 + v2;
    if (t == 255) g_partials[b] = sm[255];
}

// parallel exclusive scan of block partials (<=128 entries)
__global__ void scan2_kernel(int nblocks) {
    __shared__ int sm[128];
    int t = threadIdx.x;
    int v = (t < nblocks) ? g_partials[t] : 0;
    sm[t] = v;
    __syncthreads();
    for (int off = 1; off < 128; off <<= 1) {
        int y = (t >= off) ? sm[t - off] : 0;
        __syncthreads();
        sm[t] += y;
        __syncthreads();
    }
    if (t < nblocks) g_partials[t] = sm[t] - v;  // exclusive
}

__global__ void scan3_kernel() {
    int i = blockIdx.x * blockDim.x + threadIdx.x;
    if (i < N_NODES) {
        int v = g_rowptr[i] + g_partials[i >> 10];
        g_rowptr[i] = v;
        g_cursor[i] = v;
    }
    if (i == 0) g_rowptr[N_NODES] = N_EDGES;
}

__global__ void scatter_kernel(const int* __restrict__ src, const int* __restrict__ dst) {
    int i = blockIdx.x * blockDim.x + threadIdx.x;
    if (i < N_EDGES) {
        int p = atomicAdd(&g_cursor[dst[i]], 1);
        g_esrc[p] = src[i];
    }
}

// ---------------- GEMM: g_hlin[M,128] = A[M,128] @ W[128,128] + b ------------
// 256 threads, tile 64 rows x 128 cols; packed f32x2 FMA mainloop.
// in_id: 6 = external x pointer (use xin), else buf_ptr(in_id).
__global__ void gemm128_kernel(const float* __restrict__ xin, int in_id,
                               const float* __restrict__ W,
                               const float* __restrict__ bias, int M) {
    __shared__ float Ws[64 * 128];   // W[k0+0..63][0..127]
    __shared__ float As[64 * 64];    // A[rows][k0+0..63]
    const float* A = (in_id == 6) ? xin : buf_ptr(in_id);
    float* C = g_hlin;
    int tx = threadIdx.x;
    int row0 = blockIdx.x * 64;

    int tm = tx >> 5;   // warp id: 8 rows each
    int tn = tx & 31;   // lane: 4 cols each
    float4 bb = ((const float4*)bias)[tn];
    unsigned long long b01, b23;
    asm("mov.b64 %0, {%1, %2};" : "=l"(b01) : "f"(bb.x), "f"(bb.y));
    asm("mov.b64 %0, {%1, %2};" : "=l"(b23) : "f"(bb.z), "f"(bb.w));
    unsigned long long acc01[8], acc23[8];
    #pragma unroll
    for (int r = 0; r < 8; r++) { acc01[r] = b01; acc23[r] = b23; }

    for (int kp = 0; kp < 2; kp++) {
        int k0 = kp * 64;
        const float4* W4 = (const float4*)(W + (size_t)k0 * 128);
        float4* Ws4 = (float4*)Ws;
        #pragma unroll
        for (int i = tx; i < 64 * 32; i += 256) Ws4[i] = W4[i];
        float4* As4 = (float4*)As;
        #pragma unroll
        for (int i = tx; i < 64 * 16; i += 256) {
            int r = i >> 4, c = i & 15;
            float4 v = make_float4(0.f, 0.f, 0.f, 0.f);
            if (row0 + r < M) v = ((const float4*)(A + (size_t)(row0 + r) * 128 + k0))[c];
            As4[i] = v;
        }
        __syncthreads();

        #pragma unroll 8
        for (int k = 0; k < 64; k++) {
            float4 w = ((float4*)Ws)[k * 32 + tn];
            unsigned long long w01, w23;
            asm("mov.b64 %0, {%1, %2};" : "=l"(w01) : "f"(w.x), "f"(w.y));
            asm("mov.b64 %0, {%1, %2};" : "=l"(w23) : "f"(w.z), "f"(w.w));
            #pragma unroll
            for (int r = 0; r < 8; r++) {
                float a = As[(tm * 8 + r) * 64 + k];
                unsigned long long a2;
                asm("mov.b64 %0, {%1, %1};" : "=l"(a2) : "f"(a));
                asm("fma.rn.f32x2 %0, %1, %2, %0;" : "+l"(acc01[r]) : "l"(a2), "l"(w01));
                asm("fma.rn.f32x2 %0, %1, %2, %0;" : "+l"(acc23[r]) : "l"(a2), "l"(w23));
            }
        }
        __syncthreads();
    }

    #pragma unroll
    for (int r = 0; r < 8; r++) {
        int row = row0 + tm * 8 + r;
        if (row < M) {
            float o0, o1, o2, o3;
            asm("mov.b64 {%0, %1}, %2;" : "=f"(o0), "=f"(o1) : "l"(acc01[r]));
            asm("mov.b64 {%0, %1}, %2;" : "=f"(o2), "=f"(o3) : "l"(acc23[r]));
            ((float4*)C)[(size_t)row * 32 + tn] = make_float4(o0, o1, o2, o3);
        }
    }
}

// ---------------- aggregation: pull-style mean + leaky relu ------------------
// one warp per node; lane owns float4 (4 consecutive features)
__global__ void agg_kernel(int out_id, int do_resid) {
    int node = (blockIdx.x * blockDim.x + threadIdx.x) >> 5;
    int lane = threadIdx.x & 31;
    if (node >= N_NODES) return;
    const float* hlin = g_hlin;
    float* out = buf_ptr(out_id);
    int s0 = g_rowptr[node];
    int s1 = g_rowptr[node + 1];
    float4 acc = make_float4(0.f, 0.f, 0.f, 0.f);
    for (int e = s0; e < s1; e++) {
        int s = g_esrc[e];
        float4 v = __ldg(((const float4*)(hlin + (size_t)s * HID)) + lane);
        acc.x += v.x; acc.y += v.y; acc.z += v.z; acc.w += v.w;
    }
    float inv = 1.0f / fmaxf((float)(s1 - s0), 1.0f);
    acc.x *= inv; acc.y *= inv; acc.z *= inv; acc.w *= inv;
    acc.x = (acc.x > 0.f) ? acc.x : ALPHA * acc.x;
    acc.y = (acc.y > 0.f) ? acc.y : ALPHA * acc.y;
    acc.z = (acc.z > 0.f) ? acc.z : ALPHA * acc.z;
    acc.w = (acc.w > 0.f) ? acc.w : ALPHA * acc.w;
    ((float4*)out)[(size_t)node * 32 + lane] = acc;
    if (do_resid) {
        float4 r = ((const float4*)g_h0)[(size_t)node * 32 + lane];
        r.x += acc.x; r.y += acc.y; r.z += acc.z; r.w += acc.w;
        ((float4*)g_h3)[(size_t)node * 32 + lane] = r;
    }
}

// ---------------- segment-max pooling (sorted-batch running max) --------------
#define NODES_PER_BLOCK 128
__global__ void pool_kernel(const int* __restrict__ batch) {
    int t = threadIdx.x;
    int n0 = blockIdx.x * NODES_PER_BLOCK;
    int n1 = n0 + NODES_PER_BLOCK;
    if (n1 > N_NODES) n1 = N_NODES;
    if (n0 >= N_NODES) return;

    const float* srcp;
    int off;
    if (t < 32)      { srcp = g_ht; off = t; }
    else if (t < 64) { srcp = g_h1; off = t - 32; }
    else if (t < 96) { srcp = g_h2; off = t - 64; }
    else             { srcp = g_h3; off = t - 96; }

    const float NEG = -__int_as_float(0x7f800000);  // -inf
    float4 acc = make_float4(NEG, NEG, NEG, NEG);
    int cur = batch[n0];

    for (int n = n0; n < n1; n++) {
        int g = batch[n];   // uniform across block (sorted batch)
        if (g != cur) {
            unsigned* p = &g_pool[cur * 512 + t * 4];
            atomicMax(p + 0, f2ord(acc.x));
            atomicMax(p + 1, f2ord(acc.y));
            atomicMax(p + 2, f2ord(acc.z));
            atomicMax(p + 3, f2ord(acc.w));
            acc = make_float4(NEG, NEG, NEG, NEG);
            cur = g;
        }
        float4 v = ((const float4*)(srcp + (size_t)n * HID))[off];
        acc.x = fmaxf(acc.x, v.x);
        acc.y = fmaxf(acc.y, v.y);
        acc.z = fmaxf(acc.z, v.z);
        acc.w = fmaxf(acc.w, v.w);
    }
    unsigned* p = &g_pool[cur * 512 + t * 4];
    atomicMax(p + 0, f2ord(acc.x));
    atomicMax(p + 1, f2ord(acc.y));
    atomicMax(p + 2, f2ord(acc.z));
    atomicMax(p + 3, f2ord(acc.w));
}

// ---------------- MLP head ---------------------------------------------------
__global__ void mlp_kernel(const float* __restrict__ Wm1, const float* __restrict__ bm1,
                           const float* __restrict__ gamma, const float* __restrict__ beta,
                           const float* __restrict__ Wm2, const float* __restrict__ bm2,
                           float* __restrict__ out) {
    __shared__ float ps[512];
    __shared__ float zs[128];
    int g = blockIdx.x;
    int t = threadIdx.x;
    for (int i = t; i < 512; i += 128) ps[i] = ord2f(g_pool[g * 512 + i]);
    __syncthreads();
    float acc = bm1[t];
    #pragma unroll 8
    for (int i = 0; i < 512; i++) acc += ps[i] * Wm1[i * 128 + t];
    const float rs = rsqrtf(1.0f + 1e-5f);
    acc = (acc * gamma[t]) * rs + beta[t];
    zs[t] = fmaxf(acc, 0.0f);
    __syncthreads();
    if (t < N_CLS) {
        float o = bm2[t];
        #pragma unroll 8
        for (int k = 0; k < 128; k++) o += zs[k] * Wm2[k * N_CLS + t];
        out[g * N_CLS + t] = o;
    }
}

// ---------------- launch -----------------------------------------------------
extern "C" void kernel_launch(void* const* d_in, const int* in_sizes, int n_in,
                              void* d_out, int out_size) {
    (void)in_sizes; (void)n_in; (void)out_size;
    const float* x     = (const float*)d_in[0];
    const int*   ei    = (const int*)d_in[1];
    const int*   batch = (const int*)d_in[2];
    const float* W0 = (const float*)d_in[3];
    const float* b0 = (const float*)d_in[4];
    const float* W1 = (const float*)d_in[5];
    const float* b1 = (const float*)d_in[6];
    const float* W2 = (const float*)d_in[7];
    const float* b2 = (const float*)d_in[8];
    const float* W3 = (const float*)d_in[9];
    const float* b3 = (const float*)d_in[10];
    const float* Wm1 = (const float*)d_in[11];
    const float* bm1 = (const float*)d_in[12];
    const float* gamma = (const float*)d_in[13];
    const float* beta  = (const float*)d_in[14];
    const float* Wm2 = (const float*)d_in[15];
    const float* bm2 = (const float*)d_in[16];
    float* out = (float*)d_out;

    const int* src = ei;
    const int* dst = ei + N_EDGES;

    const int SCAN_BLOCKS = (N_NODES + 1023) / 1024;  // 98

    // CSR build
    init_kernel<<<(N_GRAPHS * 4 * HID + 255) / 256, 256>>>();
    hist_kernel<<<(N_EDGES + 255) / 256, 256>>>(dst);
    scan1_kernel<<<SCAN_BLOCKS, 256>>>();
    scan2_kernel<<<1, 128>>>(SCAN_BLOCKS);
    scan3_kernel<<<(N_NODES + 255) / 256, 256>>>();
    scatter_kernel<<<(N_EDGES + 255) / 256, 256>>>(src, dst);

    const int GEMM_GRID = (N_NODES + 63) / 64;
    const int AGG_GRID  = (N_NODES * 32 + 255) / 256;

    // buffer ids: 0=hlin 1=h0 2=h1 3=h2 4=h3 5=ht 6=external x
    gemm128_kernel<<<GEMM_GRID, 256>>>(x, 6, W0, b0, N_NODES);
    agg_kernel<<<AGG_GRID, 256>>>(1, 0);
    gemm128_kernel<<<GEMM_GRID, 256>>>(nullptr, 1, W1, b1, N_NODES);
    agg_kernel<<<AGG_GRID, 256>>>(2, 0);
    gemm128_kernel<<<GEMM_GRID, 256>>>(nullptr, 2, W2, b2, N_NODES);
    agg_kernel<<<AGG_GRID, 256>>>(3, 1);
    gemm128_kernel<<<GEMM_GRID, 256>>>(nullptr, 4, W3, b3, N_NODES);
    agg_kernel<<<AGG_GRID, 256>>>(5, 0);

    // pooling + head MLP
    pool_kernel<<<(N_NODES + NODES_PER_BLOCK - 1) / NODES_PER_BLOCK, 128>>>(batch);
    mlp_kernel<<<N_GRAPHS, 128>>>(Wm1, bm1, gamma, beta, Wm2, bm2, out);
}